// round 2
// baseline (speedup 1.0000x reference)
#include <cuda_runtime.h>
#include <math.h>

#define NFEAT 18
#define NTRK  1500
#define BSZ   64
#define NTRACK (BSZ*NTRK)        // 96000
#define LHID  128
#define HID   256
#define TSTEPS 6
#define NT_TILE 16
#define CTA_THREADS 128

// output layout offsets (floats)
#define OUT_POS   24576000       // 96000*256
#define OUT_LOGPT 36864000       // + 96000*128
#define OUT_ETA   36960000
#define OUT_PHI   37056000

// ---------------- device scratch (transposed weights) ----------------
__device__ __align__(16) float g_wt_ih0[2   * 512];   // [k][j*4+g]
__device__ __align__(16) float g_wt_hh0[128 * 512];
__device__ __align__(16) float g_wt_ih1[128 * 512];
__device__ __align__(16) float g_wt_hh1[128 * 512];
__device__ __align__(16) float g_w0t  [131 * 256];    // [k][j*2+gg]
__device__ __align__(16) float g_w1t  [256 * 256];
__device__ __align__(16) float g_b0c  [512];          // [j*4+g] = b_ih+b_hh
__device__ __align__(16) float g_b1c  [512];
__device__ __align__(16) float g_mb0c [256];          // [j*2+gg]
__device__ __align__(16) float g_mb1c [256];

// ---------------- prep: transpose weights into k-major layouts ----------------
__global__ void prep_kernel(const float* __restrict__ W_ih0, const float* __restrict__ W_hh0,
                            const float* __restrict__ b_ih0, const float* __restrict__ b_hh0,
                            const float* __restrict__ W_ih1, const float* __restrict__ W_hh1,
                            const float* __restrict__ b_ih1, const float* __restrict__ b_hh1,
                            const float* __restrict__ mw0,   const float* __restrict__ mb0,
                            const float* __restrict__ mw1,   const float* __restrict__ mb1)
{
    int stride = gridDim.x * blockDim.x;
    int idx0 = blockIdx.x * blockDim.x + threadIdx.x;

    for (int i = idx0; i < 128 * 512; i += stride) {
        int k = i >> 9, r = i & 511, j = r >> 2, g = r & 3;
        int row = g * 128 + j;
        g_wt_hh0[i] = W_hh0[row * 128 + k];
        g_wt_ih1[i] = W_ih1[row * 128 + k];
        g_wt_hh1[i] = W_hh1[row * 128 + k];
    }
    for (int i = idx0; i < 2 * 512; i += stride) {
        int k = i >> 9, r = i & 511, j = r >> 2, g = r & 3;
        g_wt_ih0[i] = W_ih0[(g * 128 + j) * 2 + k];
    }
    for (int i = idx0; i < 131 * 256; i += stride) {
        int k = i >> 8, r = i & 255, j = r >> 1, gg = r & 1;
        g_w0t[i] = mw0[(gg * 128 + j) * 131 + k];
    }
    for (int i = idx0; i < 256 * 256; i += stride) {
        int k = i >> 8, r = i & 255, j = r >> 1, gg = r & 1;
        g_w1t[i] = mw1[(gg * 128 + j) * 256 + k];
    }
    for (int i = idx0; i < 512; i += stride) {
        int j = i >> 2, g = i & 3;
        g_b0c[i] = b_ih0[g * 128 + j] + b_hh0[g * 128 + j];
        g_b1c[i] = b_ih1[g * 128 + j] + b_hh1[g * 128 + j];
    }
    for (int i = idx0; i < 256; i += stride) {
        int j = i >> 1, gg = i & 1;
        g_mb0c[i] = mb0[gg * 128 + j];
        g_mb1c[i] = mb1[gg * 128 + j];
    }
}

// ---------------- activations ----------------
__device__ __forceinline__ float sigf(float x) { return 1.0f / (1.0f + __expf(-x)); }
__device__ __forceinline__ float tanh_fast(float x) {
    float ax = fabsf(x);
    float t = __expf(-2.0f * ax);
    float r = (1.0f - t) / (1.0f + t);
    return copysignf(r, x);
}

// ---------------- inner GEMM helpers ----------------
// acc[g][n] += wt[k][4j+g] * hbuf[k][n], k = 0..127
__device__ __forceinline__ void gate_gemm(float acc[4][NT_TILE],
                                          const float* __restrict__ wt,
                                          const float (&hbuf)[128][20], int j)
{
#pragma unroll 4
    for (int k = 0; k < 128; ++k) {
        float4 w = *reinterpret_cast<const float4*>(wt + k * 512 + 4 * j);
#pragma unroll
        for (int q = 0; q < 4; ++q) {
            float4 hv = *reinterpret_cast<const float4*>(&hbuf[k][4 * q]);
            float hvv[4] = {hv.x, hv.y, hv.z, hv.w};
#pragma unroll
            for (int u = 0; u < 4; ++u) {
                int n = 4 * q + u;
                acc[0][n] = fmaf(w.x, hvv[u], acc[0][n]);
                acc[1][n] = fmaf(w.y, hvv[u], acc[1][n]);
                acc[2][n] = fmaf(w.z, hvv[u], acc[2][n]);
                acc[3][n] = fmaf(w.w, hvv[u], acc[3][n]);
            }
        }
    }
}

// a0/a1[n] += wt[k][2j+gg] * hbuf[k][n], k = 0..127
__device__ __forceinline__ void mlp_gemm(float a0[NT_TILE], float a1[NT_TILE],
                                         const float* __restrict__ wt,
                                         const float (&hbuf)[128][20], int j)
{
#pragma unroll 4
    for (int k = 0; k < 128; ++k) {
        float2 w = *reinterpret_cast<const float2*>(wt + k * 256 + 2 * j);
#pragma unroll
        for (int q = 0; q < 4; ++q) {
            float4 hv = *reinterpret_cast<const float4*>(&hbuf[k][4 * q]);
            float hvv[4] = {hv.x, hv.y, hv.z, hv.w};
#pragma unroll
            for (int u = 0; u < 4; ++u) {
                int n = 4 * q + u;
                a0[n] = fmaf(w.x, hvv[u], a0[n]);
                a1[n] = fmaf(w.y, hvv[u], a1[n]);
            }
        }
    }
}

// ---------------- fused LSTM(2 layers, 6 steps) + MLP ----------------
__global__ void __launch_bounds__(CTA_THREADS, 4)
lstm_mlp_kernel(const float* __restrict__ tf, float* __restrict__ out)
{
    const int j = threadIdx.x;                 // hidden unit 0..127
    const int track0 = blockIdx.x * NT_TILE;

    __shared__ float h0[128][20];              // pad 20 for bank-friendly layout
    __shared__ float h1[128][20];
    __shared__ float m2[128][20];
    __shared__ float xin[NT_TILE][12];
    __shared__ float f3[NT_TILE][4];

    for (int i = j; i < NT_TILE * 12; i += CTA_THREADS) {
        int n = i / 12, f = i % 12;
        int gt = track0 + n, b = gt / NTRK, t = gt - b * NTRK;
        xin[n][f] = tf[((size_t)b * NFEAT + 6 + f) * NTRK + t];
    }
    for (int i = j; i < NT_TILE * 3; i += CTA_THREADS) {
        int n = i / 3, f = i % 3;
        int gt = track0 + n, b = gt / NTRK, t = gt - b * NTRK;
        f3[n][f] = tf[((size_t)b * NFEAT + f) * NTRK + t];
    }

    float c0[NT_TILE], c1[NT_TILE];
#pragma unroll
    for (int n = 0; n < NT_TILE; ++n) { c0[n] = 0.f; c1[n] = 0.f; h0[j][n] = 0.f; h1[j][n] = 0.f; }
    __syncthreads();

    const float4 bias0 = *reinterpret_cast<const float4*>(g_b0c + 4 * j);
    const float4 bias1 = *reinterpret_cast<const float4*>(g_b1c + 4 * j);

    for (int t = 0; t < TSTEPS; ++t) {
        // ------- layer 0 -------
        float acc[4][NT_TILE];
#pragma unroll
        for (int n = 0; n < NT_TILE; ++n) {
            acc[0][n] = bias0.x; acc[1][n] = bias0.y; acc[2][n] = bias0.z; acc[3][n] = bias0.w;
        }
#pragma unroll
        for (int k = 0; k < 2; ++k) {          // tiny input GEMM (x dim = 2)
            float4 w = *reinterpret_cast<const float4*>(g_wt_ih0 + k * 512 + 4 * j);
#pragma unroll
            for (int n = 0; n < NT_TILE; ++n) {
                float xv = xin[n][2 * t + k];
                acc[0][n] = fmaf(w.x, xv, acc[0][n]);
                acc[1][n] = fmaf(w.y, xv, acc[1][n]);
                acc[2][n] = fmaf(w.z, xv, acc[2][n]);
                acc[3][n] = fmaf(w.w, xv, acc[3][n]);
            }
        }
        gate_gemm(acc, g_wt_hh0, h0, j);

        float hnew[NT_TILE];
#pragma unroll
        for (int n = 0; n < NT_TILE; ++n) {
            float ii = sigf(acc[0][n]), ff = sigf(acc[1][n]);
            float gg = tanh_fast(acc[2][n]), oo = sigf(acc[3][n]);
            c0[n] = ff * c0[n] + ii * gg;
            hnew[n] = oo * tanh_fast(c0[n]);
        }
        __syncthreads();
#pragma unroll
        for (int n = 0; n < NT_TILE; ++n) h0[j][n] = hnew[n];
        __syncthreads();

        // ------- layer 1 -------
#pragma unroll
        for (int n = 0; n < NT_TILE; ++n) {
            acc[0][n] = bias1.x; acc[1][n] = bias1.y; acc[2][n] = bias1.z; acc[3][n] = bias1.w;
        }
        gate_gemm(acc, g_wt_ih1, h0, j);
        gate_gemm(acc, g_wt_hh1, h1, j);
#pragma unroll
        for (int n = 0; n < NT_TILE; ++n) {
            float ii = sigf(acc[0][n]), ff = sigf(acc[1][n]);
            float gg = tanh_fast(acc[2][n]), oo = sigf(acc[3][n]);
            c1[n] = ff * c1[n] + ii * gg;
            hnew[n] = oo * tanh_fast(c1[n]);
        }
        __syncthreads();
#pragma unroll
        for (int n = 0; n < NT_TILE; ++n) h1[j][n] = hnew[n];
        __syncthreads();
    }

    // ------- MLP layer 0: (3 + 128) -> 256, ReLU -------
    float a0[NT_TILE], a1[NT_TILE];
    const float2 mb0 = *reinterpret_cast<const float2*>(g_mb0c + 2 * j);
#pragma unroll
    for (int n = 0; n < NT_TILE; ++n) { a0[n] = mb0.x; a1[n] = mb0.y; }
#pragma unroll
    for (int k = 0; k < 3; ++k) {
        float2 w = *reinterpret_cast<const float2*>(g_w0t + k * 256 + 2 * j);
#pragma unroll
        for (int n = 0; n < NT_TILE; ++n) {
            float xv = f3[n][k];
            a0[n] = fmaf(w.x, xv, a0[n]);
            a1[n] = fmaf(w.y, xv, a1[n]);
        }
    }
    mlp_gemm(a0, a1, g_w0t + 3 * 256, h1, j);
    // safe to overwrite h0/m2: all h0 reads finished before the last barrier
#pragma unroll
    for (int n = 0; n < NT_TILE; ++n) {
        h0[j][n] = fmaxf(a0[n], 0.f);          // hidden units 0..127
        m2[j][n] = fmaxf(a1[n], 0.f);          // hidden units 128..255
    }
    __syncthreads();

    // ------- MLP layer 1: 256 -> 256 -------
    const float2 mb1 = *reinterpret_cast<const float2*>(g_mb1c + 2 * j);
#pragma unroll
    for (int n = 0; n < NT_TILE; ++n) { a0[n] = mb1.x; a1[n] = mb1.y; }
    mlp_gemm(a0, a1, g_w1t,             h0, j);
    mlp_gemm(a0, a1, g_w1t + 128 * 256, m2, j);

#pragma unroll
    for (int n = 0; n < NT_TILE; ++n) {
        size_t gt = (size_t)(track0 + n);
        out[gt * HID + j]       = a0[n];
        out[gt * HID + 128 + j] = a1[n];
    }
}

// ---------------- pos encoding ----------------
__global__ void pos_kernel(const float* __restrict__ tf, float* __restrict__ out)
{
    int idx = blockIdx.x * blockDim.x + threadIdx.x;
    if (idx >= NTRACK * 128) return;
    int gt = idx >> 7;
    int fi = idx & 127;
    int b = gt / NTRK, t = gt - b * NTRK;
    int coord = (fi < 64) ? 3 : 4;             // eta then phi
    float x = tf[((size_t)b * NFEAT + coord) * NTRK + t];
    int f = fi & 63;
    float e = (float)(2 * (f >> 1)) * (1.0f / 64.0f);
    float dim = powf(10000.0f, e);
    float p = x * 6.283185307179586f / dim;
    float v = (f & 1) ? cosf(p) : sinf(p);
    out[(size_t)OUT_POS + (size_t)gt * 128 + fi] = v;
}

// ---------------- logpt / eta / phi passthrough ----------------
__global__ void scal_kernel(const float* __restrict__ tf, float* __restrict__ out)
{
    int gt = blockIdx.x * blockDim.x + threadIdx.x;
    if (gt >= NTRACK) return;
    int b = gt / NTRK, t = gt - b * NTRK;
    out[OUT_LOGPT + gt] = tf[((size_t)b * NFEAT + 2) * NTRK + t];
    out[OUT_ETA   + gt] = tf[((size_t)b * NFEAT + 3) * NTRK + t];
    out[OUT_PHI   + gt] = tf[((size_t)b * NFEAT + 4) * NTRK + t];
}

// ---------------- launch ----------------
extern "C" void kernel_launch(void* const* d_in, const int* in_sizes, int n_in,
                              void* d_out, int out_size)
{
    (void)in_sizes; (void)n_in; (void)out_size;
    const float* tf = (const float*)d_in[0];
    float* out = (float*)d_out;

    prep_kernel<<<256, 256>>>(
        (const float*)d_in[1], (const float*)d_in[2], (const float*)d_in[3], (const float*)d_in[4],
        (const float*)d_in[5], (const float*)d_in[6], (const float*)d_in[7], (const float*)d_in[8],
        (const float*)d_in[9], (const float*)d_in[10], (const float*)d_in[11], (const float*)d_in[12]);

    lstm_mlp_kernel<<<NTRACK / NT_TILE, CTA_THREADS>>>(tf, out);
    pos_kernel<<<(NTRACK * 128 + 255) / 256, 256>>>(tf, out);
    scal_kernel<<<(NTRACK + 255) / 256, 256>>>(tf, out);
}

// round 3
// speedup vs baseline: 1.1746x; 1.1746x over previous
#include <cuda_runtime.h>
#include <math.h>

#define NFEAT 18
#define NTRK  1500
#define BSZ   64
#define NTRACK (BSZ*NTRK)        // 96000
#define LHID  128
#define HID   256
#define TSTEPS 6
#define NT_TILE 16
#define NPAIR   8                // NT_TILE/2 f32x2 pairs
#define CTA_THREADS 128

// output layout offsets (floats)
#define OUT_POS   24576000       // 96000*256
#define OUT_LOGPT 36864000       // + 96000*128
#define OUT_ETA   36960000
#define OUT_PHI   37056000

typedef unsigned long long u64;

// ---------------- device scratch (transposed weights) ----------------
__device__ __align__(16) float g_wt_ih0[2   * 512];   // [k][j*4+g]
__device__ __align__(16) float g_wt_hh0[128 * 512];
__device__ __align__(16) float g_wt_ih1[128 * 512];
__device__ __align__(16) float g_wt_hh1[128 * 512];
__device__ __align__(16) float g_w0t  [131 * 256];    // [k][j*2+gg]
__device__ __align__(16) float g_w1t  [256 * 256];
__device__ __align__(16) float g_b0c  [512];          // [j*4+g] = b_ih+b_hh
__device__ __align__(16) float g_b1c  [512];
__device__ __align__(16) float g_mb0c [256];          // [j*2+gg]
__device__ __align__(16) float g_mb1c [256];
__device__ float g_posmul[64];                        // 2*pi / dim_t[f]

// ---------------- prep: transpose weights into k-major layouts ----------------
__global__ void prep_kernel(const float* __restrict__ W_ih0, const float* __restrict__ W_hh0,
                            const float* __restrict__ b_ih0, const float* __restrict__ b_hh0,
                            const float* __restrict__ W_ih1, const float* __restrict__ W_hh1,
                            const float* __restrict__ b_ih1, const float* __restrict__ b_hh1,
                            const float* __restrict__ mw0,   const float* __restrict__ mb0,
                            const float* __restrict__ mw1,   const float* __restrict__ mb1)
{
    int stride = gridDim.x * blockDim.x;
    int idx0 = blockIdx.x * blockDim.x + threadIdx.x;

    for (int i = idx0; i < 128 * 512; i += stride) {
        int k = i >> 9, r = i & 511, j = r >> 2, g = r & 3;
        int row = g * 128 + j;
        g_wt_hh0[i] = W_hh0[row * 128 + k];
        g_wt_ih1[i] = W_ih1[row * 128 + k];
        g_wt_hh1[i] = W_hh1[row * 128 + k];
    }
    for (int i = idx0; i < 2 * 512; i += stride) {
        int k = i >> 9, r = i & 511, j = r >> 2, g = r & 3;
        g_wt_ih0[i] = W_ih0[(g * 128 + j) * 2 + k];
    }
    for (int i = idx0; i < 131 * 256; i += stride) {
        int k = i >> 8, r = i & 255, j = r >> 1, gg = r & 1;
        g_w0t[i] = mw0[(gg * 128 + j) * 131 + k];
    }
    for (int i = idx0; i < 256 * 256; i += stride) {
        int k = i >> 8, r = i & 255, j = r >> 1, gg = r & 1;
        g_w1t[i] = mw1[(gg * 128 + j) * 256 + k];
    }
    for (int i = idx0; i < 512; i += stride) {
        int j = i >> 2, g = i & 3;
        g_b0c[i] = b_ih0[g * 128 + j] + b_hh0[g * 128 + j];
        g_b1c[i] = b_ih1[g * 128 + j] + b_hh1[g * 128 + j];
    }
    for (int i = idx0; i < 256; i += stride) {
        int j = i >> 1, gg = i & 1;
        g_mb0c[i] = mb0[gg * 128 + j];
        g_mb1c[i] = mb1[gg * 128 + j];
    }
    for (int i = idx0; i < 64; i += stride) {
        float e = (float)(2 * (i >> 1)) * (1.0f / 64.0f);
        g_posmul[i] = 6.283185307179586f / powf(10000.0f, e);
    }
}

// ---------------- f32x2 helpers ----------------
__device__ __forceinline__ u64 pack2(float x) {
    u64 r; asm("mov.b64 %0, {%1, %1};" : "=l"(r) : "f"(x)); return r;
}
__device__ __forceinline__ void unpack2(u64 v, float &lo, float &hi) {
    asm("mov.b64 {%0, %1}, %2;" : "=f"(lo), "=f"(hi) : "l"(v));
}
__device__ __forceinline__ void ffma2(u64 &d, u64 a, u64 b) {
    asm("fma.rn.f32x2 %0, %1, %2, %0;" : "+l"(d) : "l"(a), "l"(b));
}

// ---------------- activations ----------------
__device__ __forceinline__ float sigf(float x) { return 1.0f / (1.0f + __expf(-x)); }
__device__ __forceinline__ float tanh_fast(float x) {
    float ax = fabsf(x);
    float t = __expf(-2.0f * ax);
    float r = (1.0f - t) / (1.0f + t);
    return copysignf(r, x);
}

// ---------------- inner GEMM helpers (packed f32x2) ----------------
// acc[g][q] (pair n=2q,2q+1) += wt[k][4j+g] * hbuf[k][2q..2q+1], k = 0..127
__device__ __forceinline__ void gate_gemm(u64 acc[4][NPAIR],
                                          const float* __restrict__ wt,
                                          const float (&hbuf)[128][20], int j)
{
#pragma unroll 4
    for (int k = 0; k < 128; ++k) {
        float4 w = *reinterpret_cast<const float4*>(wt + k * 512 + 4 * j);
        u64 w0 = pack2(w.x), w1 = pack2(w.y), w2 = pack2(w.z), w3 = pack2(w.w);
#pragma unroll
        for (int q = 0; q < 4; ++q) {
            ulonglong2 hv = *reinterpret_cast<const ulonglong2*>(&hbuf[k][4 * q]);
            ffma2(acc[0][2 * q], w0, hv.x); ffma2(acc[0][2 * q + 1], w0, hv.y);
            ffma2(acc[1][2 * q], w1, hv.x); ffma2(acc[1][2 * q + 1], w1, hv.y);
            ffma2(acc[2][2 * q], w2, hv.x); ffma2(acc[2][2 * q + 1], w2, hv.y);
            ffma2(acc[3][2 * q], w3, hv.x); ffma2(acc[3][2 * q + 1], w3, hv.y);
        }
    }
}

// a0/a1[q] += wt[k][2j+gg] * hbuf[k][pair q], k = 0..127
__device__ __forceinline__ void mlp_gemm(u64 a0[NPAIR], u64 a1[NPAIR],
                                         const float* __restrict__ wt,
                                         const float (&hbuf)[128][20], int j)
{
#pragma unroll 4
    for (int k = 0; k < 128; ++k) {
        float2 w = *reinterpret_cast<const float2*>(wt + k * 256 + 2 * j);
        u64 w0 = pack2(w.x), w1 = pack2(w.y);
#pragma unroll
        for (int q = 0; q < 4; ++q) {
            ulonglong2 hv = *reinterpret_cast<const ulonglong2*>(&hbuf[k][4 * q]);
            ffma2(a0[2 * q], w0, hv.x); ffma2(a0[2 * q + 1], w0, hv.y);
            ffma2(a1[2 * q], w1, hv.x); ffma2(a1[2 * q + 1], w1, hv.y);
        }
    }
}

// ---------------- fused LSTM(2 layers, 6 steps) + MLP ----------------
__global__ void __launch_bounds__(CTA_THREADS, 3)
lstm_mlp_kernel(const float* __restrict__ tf, float* __restrict__ out)
{
    const int j = threadIdx.x;                 // hidden unit 0..127
    const int track0 = blockIdx.x * NT_TILE;

    __shared__ float h0[128][20];              // pad 20: 80B rows (16B multiple)
    __shared__ float h1[128][20];
    __shared__ float m2[128][20];
    __shared__ float xin[12][NT_TILE];         // feature-major: pairs contiguous in n
    __shared__ float f3s[3][NT_TILE];

    for (int i = j; i < 12 * NT_TILE; i += CTA_THREADS) {
        int f = i / NT_TILE, n = i % NT_TILE;
        int gt = track0 + n, b = gt / NTRK, t = gt - b * NTRK;
        xin[f][n] = tf[((size_t)b * NFEAT + 6 + f) * NTRK + t];
    }
    for (int i = j; i < 3 * NT_TILE; i += CTA_THREADS) {
        int f = i / NT_TILE, n = i % NT_TILE;
        int gt = track0 + n, b = gt / NTRK, t = gt - b * NTRK;
        f3s[f][n] = tf[((size_t)b * NFEAT + f) * NTRK + t];
    }

    float c0[NT_TILE], c1[NT_TILE];
#pragma unroll
    for (int n = 0; n < NT_TILE; ++n) { c0[n] = 0.f; c1[n] = 0.f; h0[j][n] = 0.f; h1[j][n] = 0.f; }
    __syncthreads();

    const float4 bias0 = *reinterpret_cast<const float4*>(g_b0c + 4 * j);
    const float4 bias1 = *reinterpret_cast<const float4*>(g_b1c + 4 * j);
    const u64 b0p[4] = { pack2(bias0.x), pack2(bias0.y), pack2(bias0.z), pack2(bias0.w) };
    const u64 b1p[4] = { pack2(bias1.x), pack2(bias1.y), pack2(bias1.z), pack2(bias1.w) };

    for (int t = 0; t < TSTEPS; ++t) {
        // ------- layer 0 -------
        u64 acc[4][NPAIR];
#pragma unroll
        for (int q = 0; q < NPAIR; ++q) {
            acc[0][q] = b0p[0]; acc[1][q] = b0p[1]; acc[2][q] = b0p[2]; acc[3][q] = b0p[3];
        }
#pragma unroll
        for (int k = 0; k < 2; ++k) {          // tiny input GEMM (x dim = 2)
            float4 w = *reinterpret_cast<const float4*>(g_wt_ih0 + k * 512 + 4 * j);
            u64 w0 = pack2(w.x), w1 = pack2(w.y), w2 = pack2(w.z), w3 = pack2(w.w);
#pragma unroll
            for (int q = 0; q < NPAIR; ++q) {
                u64 xv = *reinterpret_cast<const u64*>(&xin[2 * t + k][2 * q]);
                ffma2(acc[0][q], w0, xv);
                ffma2(acc[1][q], w1, xv);
                ffma2(acc[2][q], w2, xv);
                ffma2(acc[3][q], w3, xv);
            }
        }
        gate_gemm(acc, g_wt_hh0, h0, j);

        float hnew[NT_TILE];
#pragma unroll
        for (int q = 0; q < NPAIR; ++q) {
            float iv[2], fv[2], gv[2], ov[2];
            unpack2(acc[0][q], iv[0], iv[1]);
            unpack2(acc[1][q], fv[0], fv[1]);
            unpack2(acc[2][q], gv[0], gv[1]);
            unpack2(acc[3][q], ov[0], ov[1]);
#pragma unroll
            for (int u = 0; u < 2; ++u) {
                int n = 2 * q + u;
                float ii = sigf(iv[u]), ff = sigf(fv[u]);
                float gg = tanh_fast(gv[u]), oo = sigf(ov[u]);
                c0[n] = ff * c0[n] + ii * gg;
                hnew[n] = oo * tanh_fast(c0[n]);
            }
        }
        __syncthreads();
#pragma unroll
        for (int n = 0; n < NT_TILE; ++n) h0[j][n] = hnew[n];
        __syncthreads();

        // ------- layer 1 -------
#pragma unroll
        for (int q = 0; q < NPAIR; ++q) {
            acc[0][q] = b1p[0]; acc[1][q] = b1p[1]; acc[2][q] = b1p[2]; acc[3][q] = b1p[3];
        }
        gate_gemm(acc, g_wt_ih1, h0, j);
        gate_gemm(acc, g_wt_hh1, h1, j);
#pragma unroll
        for (int q = 0; q < NPAIR; ++q) {
            float iv[2], fv[2], gv[2], ov[2];
            unpack2(acc[0][q], iv[0], iv[1]);
            unpack2(acc[1][q], fv[0], fv[1]);
            unpack2(acc[2][q], gv[0], gv[1]);
            unpack2(acc[3][q], ov[0], ov[1]);
#pragma unroll
            for (int u = 0; u < 2; ++u) {
                int n = 2 * q + u;
                float ii = sigf(iv[u]), ff = sigf(fv[u]);
                float gg = tanh_fast(gv[u]), oo = sigf(ov[u]);
                c1[n] = ff * c1[n] + ii * gg;
                hnew[n] = oo * tanh_fast(c1[n]);
            }
        }
        __syncthreads();
#pragma unroll
        for (int n = 0; n < NT_TILE; ++n) h1[j][n] = hnew[n];
        __syncthreads();
    }

    // ------- MLP layer 0: (3 + 128) -> 256, ReLU -------
    u64 a0[NPAIR], a1[NPAIR];
    const float2 mb0 = *reinterpret_cast<const float2*>(g_mb0c + 2 * j);
    {
        u64 m0 = pack2(mb0.x), m1 = pack2(mb0.y);
#pragma unroll
        for (int q = 0; q < NPAIR; ++q) { a0[q] = m0; a1[q] = m1; }
    }
#pragma unroll
    for (int k = 0; k < 3; ++k) {
        float2 w = *reinterpret_cast<const float2*>(g_w0t + k * 256 + 2 * j);
        u64 w0 = pack2(w.x), w1 = pack2(w.y);
#pragma unroll
        for (int q = 0; q < NPAIR; ++q) {
            u64 xv = *reinterpret_cast<const u64*>(&f3s[k][2 * q]);
            ffma2(a0[q], w0, xv);
            ffma2(a1[q], w1, xv);
        }
    }
    mlp_gemm(a0, a1, g_w0t + 3 * 256, h1, j);
    // safe to overwrite h0/m2: all h0 reads finished before the last barrier
#pragma unroll
    for (int q = 0; q < NPAIR; ++q) {
        float lo, hi;
        unpack2(a0[q], lo, hi);
        h0[j][2 * q] = fmaxf(lo, 0.f); h0[j][2 * q + 1] = fmaxf(hi, 0.f);   // units 0..127
        unpack2(a1[q], lo, hi);
        m2[j][2 * q] = fmaxf(lo, 0.f); m2[j][2 * q + 1] = fmaxf(hi, 0.f);   // units 128..255
    }
    __syncthreads();

    // ------- MLP layer 1: 256 -> 256 -------
    const float2 mb1 = *reinterpret_cast<const float2*>(g_mb1c + 2 * j);
    {
        u64 m0 = pack2(mb1.x), m1 = pack2(mb1.y);
#pragma unroll
        for (int q = 0; q < NPAIR; ++q) { a0[q] = m0; a1[q] = m1; }
    }
    mlp_gemm(a0, a1, g_w1t,             h0, j);
    mlp_gemm(a0, a1, g_w1t + 128 * 256, m2, j);

#pragma unroll
    for (int q = 0; q < NPAIR; ++q) {
        float lo, hi;
        size_t gt = (size_t)(track0 + 2 * q);
        unpack2(a0[q], lo, hi);
        out[gt * HID + j]               = lo;
        out[(gt + 1) * HID + j]         = hi;
        unpack2(a1[q], lo, hi);
        out[gt * HID + 128 + j]         = lo;
        out[(gt + 1) * HID + 128 + j]   = hi;
    }
}

// ---------------- pos encoding ----------------
__global__ void pos_kernel(const float* __restrict__ tf, float* __restrict__ out)
{
    int idx = blockIdx.x * blockDim.x + threadIdx.x;
    if (idx >= NTRACK * 128) return;
    int gt = idx >> 7;
    int fi = idx & 127;
    int b = gt / NTRK, t = gt - b * NTRK;
    int coord = (fi < 64) ? 3 : 4;             // eta then phi
    float x = tf[((size_t)b * NFEAT + coord) * NTRK + t];
    int f = fi & 63;
    float p = x * g_posmul[f];
    float v = (f & 1) ? __cosf(p) : __sinf(p);
    out[(size_t)OUT_POS + (size_t)gt * 128 + fi] = v;
}

// ---------------- logpt / eta / phi passthrough ----------------
__global__ void scal_kernel(const float* __restrict__ tf, float* __restrict__ out)
{
    int gt = blockIdx.x * blockDim.x + threadIdx.x;
    if (gt >= NTRACK) return;
    int b = gt / NTRK, t = gt - b * NTRK;
    out[OUT_LOGPT + gt] = tf[((size_t)b * NFEAT + 2) * NTRK + t];
    out[OUT_ETA   + gt] = tf[((size_t)b * NFEAT + 3) * NTRK + t];
    out[OUT_PHI   + gt] = tf[((size_t)b * NFEAT + 4) * NTRK + t];
}

// ---------------- launch ----------------
extern "C" void kernel_launch(void* const* d_in, const int* in_sizes, int n_in,
                              void* d_out, int out_size)
{
    (void)in_sizes; (void)n_in; (void)out_size;
    const float* tf = (const float*)d_in[0];
    float* out = (float*)d_out;

    prep_kernel<<<256, 256>>>(
        (const float*)d_in[1], (const float*)d_in[2], (const float*)d_in[3], (const float*)d_in[4],
        (const float*)d_in[5], (const float*)d_in[6], (const float*)d_in[7], (const float*)d_in[8],
        (const float*)d_in[9], (const float*)d_in[10], (const float*)d_in[11], (const float*)d_in[12]);

    lstm_mlp_kernel<<<NTRACK / NT_TILE, CTA_THREADS>>>(tf, out);
    pos_kernel<<<(NTRACK * 128 + 255) / 256, 256>>>(tf, out);
    scal_kernel<<<(NTRACK + 255) / 256, 256>>>(tf, out);
}